// round 3
// baseline (speedup 1.0000x reference)
#include <cuda_runtime.h>
#include <math.h>

// Problem constants (from reference)
#define B 64
#define N 4096
#define D 256
#define TEMPERATURE 0.1f
#define EPS 1e-8f

// Single block, 1024 threads = 32 warps. Warp w handles samples w and w+32.
// Per sample: gather anchor/positive/negative rows (D=256 fp32 each),
// compute 5 reductions via warp shuffles, per-sample loss -> shared,
// warp 0 reduces the 64 losses and writes the mean.
__global__ __launch_bounds__(1024, 1)
void graph_contrastive_loss_kernel(const float* __restrict__ emb,
                                   const int* __restrict__ anchor_idx,
                                   const int* __restrict__ pos_idx,
                                   const int* __restrict__ neg_graph_idx,
                                   const int* __restrict__ neg_node_idx,
                                   float* __restrict__ out) {
    __shared__ float s_loss[B];

    const int tid  = threadIdx.x;
    const int wid  = tid >> 5;   // 0..31
    const int lane = tid & 31;

    #pragma unroll
    for (int rep = 0; rep < 2; ++rep) {
        const int b = wid + rep * 32;  // sample index 0..63

        // Lane 0 loads the 4 indices, broadcasts — avoids 32x redundant LDG.
        int ai = 0, pi = 0, ngi = 0, nni = 0;
        if (lane == 0) {
            ai  = anchor_idx[b];
            pi  = pos_idx[b];
            ngi = neg_graph_idx[b];
            nni = neg_node_idx[b];
        }
        ai  = __shfl_sync(0xFFFFFFFFu, ai,  0);
        pi  = __shfl_sync(0xFFFFFFFFu, pi,  0);
        ngi = __shfl_sync(0xFFFFFFFFu, ngi, 0);
        nni = __shfl_sync(0xFFFFFFFFu, nni, 0);

        const long long a_row = (long long)b * N + ai;
        const long long p_row = (long long)b * N + pi;
        const long long n_row = (long long)ngi * N + nni;

        const float4* a_ptr = (const float4*)(emb + a_row * D);
        const float4* p_ptr = (const float4*)(emb + p_row * D);
        const float4* n_ptr = (const float4*)(emb + n_row * D);

        // Each lane covers 8 floats = 2 float4 -> 64 float4 total = 256 floats
        float4 a0 = a_ptr[lane * 2];
        float4 a1 = a_ptr[lane * 2 + 1];
        float4 p0 = p_ptr[lane * 2];
        float4 p1 = p_ptr[lane * 2 + 1];
        float4 n0 = n_ptr[lane * 2];
        float4 n1 = n_ptr[lane * 2 + 1];

        float dot_ap = a0.x*p0.x + a0.y*p0.y + a0.z*p0.z + a0.w*p0.w
                     + a1.x*p1.x + a1.y*p1.y + a1.z*p1.z + a1.w*p1.w;
        float dot_an = a0.x*n0.x + a0.y*n0.y + a0.z*n0.z + a0.w*n0.w
                     + a1.x*n1.x + a1.y*n1.y + a1.z*n1.z + a1.w*n1.w;
        float na2 = a0.x*a0.x + a0.y*a0.y + a0.z*a0.z + a0.w*a0.w
                  + a1.x*a1.x + a1.y*a1.y + a1.z*a1.z + a1.w*a1.w;
        float np2 = p0.x*p0.x + p0.y*p0.y + p0.z*p0.z + p0.w*p0.w
                  + p1.x*p1.x + p1.y*p1.y + p1.z*p1.z + p1.w*p1.w;
        float nn2 = n0.x*n0.x + n0.y*n0.y + n0.z*n0.z + n0.w*n0.w
                  + n1.x*n1.x + n1.y*n1.y + n1.z*n1.z + n1.w*n1.w;

        // Warp tree reduction of all 5 scalars
        #pragma unroll
        for (int off = 16; off > 0; off >>= 1) {
            dot_ap += __shfl_down_sync(0xFFFFFFFFu, dot_ap, off);
            dot_an += __shfl_down_sync(0xFFFFFFFFu, dot_an, off);
            na2    += __shfl_down_sync(0xFFFFFFFFu, na2,    off);
            np2    += __shfl_down_sync(0xFFFFFFFFu, np2,    off);
            nn2    += __shfl_down_sync(0xFFFFFFFFu, nn2,    off);
        }

        if (lane == 0) {
            float na = fmaxf(sqrtf(na2), EPS);
            float np = fmaxf(sqrtf(np2), EPS);
            float nn = fmaxf(sqrtf(nn2), EPS);
            float pos_sim = dot_ap / (na * np) * (1.0f / TEMPERATURE);
            float neg_sim = dot_an / (na * nn) * (1.0f / TEMPERATURE);
            float x = neg_sim - pos_sim;
            // logaddexp(0, x): overflow-safe both directions
            float loss = (x > 0.0f) ? (x + log1pf(expf(-x))) : log1pf(expf(x));
            s_loss[b] = loss;
        }
    }

    __syncthreads();

    // Warp 0 reduces the 64 per-sample losses
    if (wid == 0) {
        float v = s_loss[lane] + s_loss[lane + 32];
        #pragma unroll
        for (int off = 16; off > 0; off >>= 1)
            v += __shfl_down_sync(0xFFFFFFFFu, v, off);
        if (lane == 0)
            out[0] = v * (1.0f / (float)B);
    }
}

extern "C" void kernel_launch(void* const* d_in, const int* in_sizes, int n_in,
                              void* d_out, int out_size) {
    // Input order (metadata / setup_inputs dict order):
    //   0: node_embeddings  float32 [B, N, D]
    //   1: graph_labels     int32   [B]   (unused)
    //   2: anchor_idx       int32   [B]
    //   3: pos_idx          int32   [B]
    //   4: neg_graph_idx    int32   [B]
    //   5: neg_node_idx     int32   [B]
    const float* emb          = (const float*)d_in[0];
    const int*   anchor_idx   = (const int*)d_in[2];
    const int*   pos_idx      = (const int*)d_in[3];
    const int*   neg_graph    = (const int*)d_in[4];
    const int*   neg_node     = (const int*)d_in[5];
    float* out = (float*)d_out;

    graph_contrastive_loss_kernel<<<1, 1024>>>(emb, anchor_idx, pos_idx,
                                               neg_graph, neg_node, out);
}

// round 4
// speedup vs baseline: 1.3544x; 1.3544x over previous
#include <cuda_runtime.h>
#include <math.h>

#define B 64
#define N 4096
#define D 256
#define TEMPERATURE 0.1f
#define EPS 1e-8f

// Cross-block finish scratch (allocation-free: __device__ globals).
__device__ float g_scratch[B];
__device__ unsigned int g_ticket = 0;

// 64 blocks x 32 threads. Block b computes sample b's loss with one warp
// (single dependent chain: idx loads -> 6 independent float4 row loads ->
// one 5-step shuffle reduction). Last block to finish reduces the 64
// per-sample losses and writes the mean.
__global__ __launch_bounds__(32, 1)
void graph_contrastive_loss_kernel(const float* __restrict__ emb,
                                   const int* __restrict__ anchor_idx,
                                   const int* __restrict__ pos_idx,
                                   const int* __restrict__ neg_graph_idx,
                                   const int* __restrict__ neg_node_idx,
                                   float* __restrict__ out) {
    const int b    = blockIdx.x;
    const int lane = threadIdx.x;

    // All 4 index loads are uniform-address (LSU broadcast) and independent
    // -> issued back-to-back, one memory round-trip total.
    const int ai  = anchor_idx[b];
    const int pi  = pos_idx[b];
    const int ngi = neg_graph_idx[b];
    const int nni = neg_node_idx[b];

    const float4* a_ptr = (const float4*)(emb + ((long long)b   * N + ai)  * D);
    const float4* p_ptr = (const float4*)(emb + ((long long)b   * N + pi)  * D);
    const float4* n_ptr = (const float4*)(emb + ((long long)ngi * N + nni) * D);

    // 6 independent float4 loads per lane (MLP=6) -> one DRAM round-trip.
    float4 a0 = a_ptr[lane * 2];
    float4 a1 = a_ptr[lane * 2 + 1];
    float4 p0 = p_ptr[lane * 2];
    float4 p1 = p_ptr[lane * 2 + 1];
    float4 n0 = n_ptr[lane * 2];
    float4 n1 = n_ptr[lane * 2 + 1];

    float dot_ap = a0.x*p0.x + a0.y*p0.y + a0.z*p0.z + a0.w*p0.w
                 + a1.x*p1.x + a1.y*p1.y + a1.z*p1.z + a1.w*p1.w;
    float dot_an = a0.x*n0.x + a0.y*n0.y + a0.z*n0.z + a0.w*n0.w
                 + a1.x*n1.x + a1.y*n1.y + a1.z*n1.z + a1.w*n1.w;
    float na2 = a0.x*a0.x + a0.y*a0.y + a0.z*a0.z + a0.w*a0.w
              + a1.x*a1.x + a1.y*a1.y + a1.z*a1.z + a1.w*a1.w;
    float np2 = p0.x*p0.x + p0.y*p0.y + p0.z*p0.z + p0.w*p0.w
              + p1.x*p1.x + p1.y*p1.y + p1.z*p1.z + p1.w*p1.w;
    float nn2 = n0.x*n0.x + n0.y*n0.y + n0.z*n0.z + n0.w*n0.w
              + n1.x*n1.x + n1.y*n1.y + n1.z*n1.z + n1.w*n1.w;

    #pragma unroll
    for (int off = 16; off > 0; off >>= 1) {
        dot_ap += __shfl_down_sync(0xFFFFFFFFu, dot_ap, off);
        dot_an += __shfl_down_sync(0xFFFFFFFFu, dot_an, off);
        na2    += __shfl_down_sync(0xFFFFFFFFu, na2,    off);
        np2    += __shfl_down_sync(0xFFFFFFFFu, np2,    off);
        nn2    += __shfl_down_sync(0xFFFFFFFFu, nn2,    off);
    }

    unsigned int is_last = 0;
    if (lane == 0) {
        float na = fmaxf(sqrtf(na2), EPS);
        float np = fmaxf(sqrtf(np2), EPS);
        float nn = fmaxf(sqrtf(nn2), EPS);
        float pos_sim = dot_ap / (na * np) * (1.0f / TEMPERATURE);
        float neg_sim = dot_an / (na * nn) * (1.0f / TEMPERATURE);
        float x = neg_sim - pos_sim;
        float loss = (x > 0.0f) ? (x + log1pf(expf(-x))) : log1pf(expf(x));
        g_scratch[b] = loss;
        __threadfence();                       // make scratch visible before ticket
        unsigned int t = atomicAdd(&g_ticket, 1u);
        is_last = (t == B - 1) ? 1u : 0u;
    }
    is_last = __shfl_sync(0xFFFFFFFFu, is_last, 0);

    if (is_last) {
        // Bypass L1 for peer-written scratch.
        float v = __ldcg(&g_scratch[lane]) + __ldcg(&g_scratch[lane + 32]);
        #pragma unroll
        for (int off = 16; off > 0; off >>= 1)
            v += __shfl_down_sync(0xFFFFFFFFu, v, off);
        if (lane == 0) {
            out[0] = v * (1.0f / (float)B);
            g_ticket = 0;                      // reset for next graph replay
        }
    }
}

extern "C" void kernel_launch(void* const* d_in, const int* in_sizes, int n_in,
                              void* d_out, int out_size) {
    // Input order:
    //   0: node_embeddings  float32 [B, N, D]
    //   1: graph_labels     int32   [B]   (unused)
    //   2: anchor_idx       int32   [B]
    //   3: pos_idx          int32   [B]
    //   4: neg_graph_idx    int32   [B]
    //   5: neg_node_idx     int32   [B]
    const float* emb        = (const float*)d_in[0];
    const int*   anchor_idx = (const int*)d_in[2];
    const int*   pos_idx    = (const int*)d_in[3];
    const int*   neg_graph  = (const int*)d_in[4];
    const int*   neg_node   = (const int*)d_in[5];
    float* out = (float*)d_out;

    graph_contrastive_loss_kernel<<<B, 32>>>(emb, anchor_idx, pos_idx,
                                             neg_graph, neg_node, out);
}